// round 12
// baseline (speedup 1.0000x reference)
#include <cuda_runtime.h>
#include <math.h>
#include <stdint.h>
#include <stddef.h>

// ---------------------------------------------------------------------------
// AugmentedLstm: B=64, T=512, D=512, H=512 — single fused persistent kernel.
//   Warps 0-3 (tid 0..127):  recurrence (R11 design: per-warp cp.async h
//     staging, 8-chunk k-pipeline, per-group release/acquire h counters).
//   Warps 4-7 (tid 128..255): input-projection GEMM producer. 12288 tiles of
//     [128 rows = 2t x 64b, 64 cols], t-ascending, static stride-128 queue.
//     Per-t-chunk ready counters; recurrence polls cnt[t>>1]==48.
//   proj work executes in the recurrence's idle issue slots -> overlap.
// ---------------------------------------------------------------------------

#define BDIM 64
#define TDIM 512
#define HDIM 512
#define NTOT (6 * HDIM)      // 3072
#define NCTA_B 128
#define NTCH 256             // t-chunks of 2 steps
#define NT_PER_CH 48         // 3072/64 col tiles per chunk
#define NTILES (NTCH * NT_PER_CH)

// packed fp32x2 FMA (sm_100+/sm_103a PTX; ptxas never emits it from C++)
#define FMA2(d, a, b) asm("fma.rn.f32x2 %0, %1, %2, %0;" : "+l"(d) : "l"(a), "l"(b))

__device__ __forceinline__ float f2lo(unsigned long long v) {
    return __uint_as_float((unsigned)(v & 0xffffffffull));
}
__device__ __forceinline__ float f2hi(unsigned long long v) {
    return __uint_as_float((unsigned)(v >> 32));
}
__device__ __forceinline__ float sigm(float x) { return 1.0f / (1.0f + expf(-x)); }

// ---- global scratch (no runtime allocation allowed) ----
__device__ float g_proj[(size_t)TDIM * BDIM * NTOT];  // t-major: [t*64+b][3072]
__device__ float g_hbuf[2][BDIM * HDIM];              // double-buffered h state
__device__ unsigned int g_cnt[8];                     // h-exchange group counters
__device__ unsigned int g_projcnt[NTCH];              // proj tiles done per chunk

__device__ __forceinline__ int read_len(const int* L, int b) {
    return (L[1] == 0) ? L[2 * b] : L[b];   // int64 vs int32 auto-detect
}

__device__ __forceinline__ void signal_release(unsigned* p) {
    unsigned t;
    asm volatile("atom.add.release.gpu.u32 %0, [%1], 1;" : "=r"(t) : "l"(p) : "memory");
}
__device__ __forceinline__ unsigned ld_acq(unsigned* p) {
    unsigned v;
    asm volatile("ld.acquire.gpu.u32 %0, [%1];" : "=r"(v) : "l"(p) : "memory");
    return v;
}
__device__ __forceinline__ void pollw(unsigned* p, unsigned tgt) {
    while ((int)(ld_acq(p) - tgt) < 0) { }
}

__device__ __forceinline__ void cpasync16(uint32_t dst, const float* src) {
    asm volatile("cp.async.cg.shared.global [%0], [%1], 16;" :: "r"(dst), "l"(src));
}
#define CP_COMMIT()  asm volatile("cp.async.commit_group;" ::: "memory")
#define CP_WAITG(n)  asm volatile("cp.async.wait_group " #n ";" ::: "memory")
#define NBAR(id, cnt) asm volatile("bar.sync %0, %1;" :: "r"(id), "r"(cnt) : "memory")

// SMEM layout (floats): sh_h | sh_w | sh_len | As2 | Bs
#define SH_HSTRIDE 516
#define SH_WSTRIDE 520
#define OFF_W   (BDIM * SH_HSTRIDE)                 // 33024
#define OFF_LEN (OFF_W + 20 * SH_WSTRIDE)           // 43424
#define OFF_A   (OFF_LEN + 64)                      // 43488
#define OFF_B   (OFF_A + 32 * 256)                  // 51680
#define SMEM_FLOATS (OFF_B + 32 * 64)               // 53728 -> 214912 B
#define NTHR 256

#define ISSUE_CHUNK(G) do {                                                   \
    if (ral) {                                                                \
        const float* _s = hb + ((G) << 6) + soff;                             \
        uint32_t _d = hd + (uint32_t)((((G) << 6) + soff) << 2);              \
        _Pragma("unroll")                                                     \
        for (int _i = 0; _i < 8; _i++) cpasync16(_d + (_i << 4), _s + (_i << 2)); \
    }                                                                         \
    CP_COMMIT();                                                              \
} while (0)

#define COMPUTE_CHUNK(G) do {                                                 \
    if (anyact) {                                                             \
        _Pragma("unroll 8")                                                   \
        for (int _kq = 0; _kq < 16; _kq++) {                                  \
            int _k = ((G) << 6) + (_kq << 2);                                 \
            ulonglong2 hv0 = *(const ulonglong2*)&h0[_k];                     \
            ulonglong2 hv1 = *(const ulonglong2*)&h1[_k];                     \
            _Pragma("unroll")                                                 \
            for (int _g = 0; _g < 5; _g++) {                                  \
                ulonglong2 wv =                                               \
                    *(const ulonglong2*)&sh_w[(_g * 4 + jl) * SH_WSTRIDE + _k]; \
                FMA2(acc0[_g], hv0.x, wv.x);                                  \
                FMA2(acc0[_g], hv0.y, wv.y);                                  \
                FMA2(acc1[_g], hv1.x, wv.x);                                  \
                FMA2(acc1[_g], hv1.y, wv.y);                                  \
            }                                                                 \
        }                                                                     \
    }                                                                         \
} while (0)

__global__ __launch_bounds__(NTHR, 1)
void fused_kernel(const float* __restrict__ X, const int* __restrict__ L,
                  const float* __restrict__ Wi, const float* __restrict__ Bi,
                  const float* __restrict__ Ws, const float* __restrict__ bs,
                  float* __restrict__ out)
{
    extern __shared__ float sm[];
    float* sh_h = sm;
    float* sh_w = sm + OFF_W;
    int*   sh_len = (int*)(sm + OFF_LEN);
    float* As2 = sm + OFF_A;    // proj A, duplicated pairs [k][2*m] 32x256
    float* Bs  = sm + OFF_B;    // proj B [k][n] 32x64

    const int cid = blockIdx.x;        // 0..127
    const int tid = threadIdx.x;       // 0..255

    // ---- shared setup (all 256 threads) ----
    if (tid < BDIM) sh_len[tid] = read_len(L, tid);
    for (int i = tid; i < BDIM * SH_HSTRIDE; i += NTHR) sh_h[i] = 0.0f;
    for (int idx4 = tid; idx4 < 20 * 128; idx4 += NTHR) {
        int r = idx4 >> 7;
        int k = (idx4 & 127) << 2;
        int grow = ((r >> 2) << 9) + (cid << 2) + (r & 3);
        *(float4*)&sh_w[r * SH_WSTRIDE + k] = *(const float4*)&Ws[(size_t)grow * 512 + k];
    }
    __syncthreads();   // the ONLY full-CTA barrier

    if (tid < 128) {
        // ================= recurrence role (warps 0-3) =================
        const int bp  = tid >> 2;
        const int jl  = tid & 3;
        const int b0  = bp << 1;
        const int b1  = b0 + 1;
        const int J   = (cid << 2) + jl;
        const int mygrp = cid >> 4;

        const int lane = tid & 31;
        const int wrp  = tid >> 5;
        const int srow = (wrp << 4) + (lane >> 1);
        const int soff = (lane & 1) << 5;
        const uint32_t sh_h_u32 = (uint32_t)__cvta_generic_to_shared(sh_h);

        const int len0 = sh_len[b0];
        const int len1 = sh_len[b1];
        const int wlen = sh_len[wrp << 4];
        float bias[5];
        #pragma unroll
        for (int g = 0; g < 5; g++) bias[g] = bs[g * 512 + J];
        float c0 = 0.0f, c1 = 0.0f;

        const float* h0 = &sh_h[b0 * SH_HSTRIDE];
        const float* h1 = &sh_h[b1 * SH_HSTRIDE];

        for (int t = 0; t < TDIM; t++) {
            const bool a0 = (t < len0);
            const bool a1 = (t < len1);
            const bool anyact = a0 | a1;

            // proj readiness: chunk t>>1 must be fully produced (48 tiles).
            // Active at t -> was active at t-1 -> counters monotone, so only
            // even t needs a fresh poll.
            if (anyact && !(t & 1)) pollw(&g_projcnt[t >> 1], NT_PER_CH);

            float pi0[6], pi1[6];
            if (a0) {
                const float* p = &g_proj[(size_t)((t << 6) + b0) * NTOT + J];
                #pragma unroll
                for (int g = 0; g < 6; g++) pi0[g] = p[g * 512];
            }
            if (a1) {
                const float* p = &g_proj[(size_t)((t << 6) + b1) * NTOT + J];
                #pragma unroll
                for (int g = 0; g < 6; g++) pi1[g] = p[g * 512];
            }

            unsigned long long acc0[5] = {}, acc1[5] = {};

            if (t > 0 && wlen > t) {
                const unsigned tgt = 16u * (unsigned)t;
                const bool ral = (sh_len[srow] > t);
                const float* hb = &g_hbuf[t & 1][srow << 9];
                const uint32_t hd = sh_h_u32 + (uint32_t)(srow * SH_HSTRIDE) * 4u;

                pollw(&g_cnt[0], tgt); ISSUE_CHUNK(0);
                pollw(&g_cnt[1], tgt); ISSUE_CHUNK(1);
                pollw(&g_cnt[2], tgt); ISSUE_CHUNK(2);
                CP_WAITG(2); __syncwarp(); COMPUTE_CHUNK(0);
                pollw(&g_cnt[3], tgt); ISSUE_CHUNK(3);
                CP_WAITG(2); __syncwarp(); COMPUTE_CHUNK(1);
                pollw(&g_cnt[4], tgt); ISSUE_CHUNK(4);
                CP_WAITG(2); __syncwarp(); COMPUTE_CHUNK(2);
                pollw(&g_cnt[5], tgt); ISSUE_CHUNK(5);
                CP_WAITG(2); __syncwarp(); COMPUTE_CHUNK(3);
                pollw(&g_cnt[6], tgt); ISSUE_CHUNK(6);
                CP_WAITG(2); __syncwarp(); COMPUTE_CHUNK(4);
                pollw(&g_cnt[7], tgt); ISSUE_CHUNK(7);
                CP_WAITG(2); __syncwarp(); COMPUTE_CHUNK(5);
                CP_WAITG(1); __syncwarp(); COMPUTE_CHUNK(6);
                CP_WAITG(0); __syncwarp(); COMPUTE_CHUNK(7);
            }

            float outv0 = 0.0f, outv1 = 0.0f;
            if (a0) {
                float ps[5];
                #pragma unroll
                for (int g = 0; g < 5; g++) ps[g] = f2lo(acc0[g]) + f2hi(acc0[g]) + bias[g];
                float ig = sigm(pi0[0] + ps[0]);
                float fg = sigm(pi0[1] + ps[1]);
                float gg = tanhf(pi0[2] + ps[2]);
                float og = sigm(pi0[3] + ps[3]);
                float cn = ig * gg + fg * c0;
                float ov = og * tanhf(cn);
                float hw = sigm(pi0[4] + ps[4]);
                outv0 = hw * ov + (1.0f - hw) * pi0[5];
                c0 = cn;
                __stcg(&g_hbuf[(t + 1) & 1][(b0 << 9) + J], outv0);
            } else c0 = 0.0f;
            if (a1) {
                float ps[5];
                #pragma unroll
                for (int g = 0; g < 5; g++) ps[g] = f2lo(acc1[g]) + f2hi(acc1[g]) + bias[g];
                float ig = sigm(pi1[0] + ps[0]);
                float fg = sigm(pi1[1] + ps[1]);
                float gg = tanhf(pi1[2] + ps[2]);
                float og = sigm(pi1[3] + ps[3]);
                float cn = ig * gg + fg * c1;
                float ov = og * tanhf(cn);
                float hw = sigm(pi1[4] + ps[4]);
                outv1 = hw * ov + (1.0f - hw) * pi1[5];
                c1 = cn;
                __stcg(&g_hbuf[(t + 1) & 1][(b1 << 9) + J], outv1);
            } else c1 = 0.0f;
            out[(size_t)((b0 << 9) + t) * HDIM + J] = outv0;
            out[(size_t)((b1 << 9) + t) * HDIM + J] = outv1;

            NBAR(1, 128);                       // lstm warps only
            if (tid == 0 && t != TDIM - 1) signal_release(&g_cnt[mygrp]);
        }
    } else {
        // ================= proj producer role (warps 4-7) =================
        const int tid2 = tid - 128;        // 0..127
        const int tm = tid2 >> 3;          // 0..15  (8 rows each)
        const int tn = tid2 & 7;           // 0..7   (8 cols each)
        const int maxl = sh_len[0];        // lengths sorted descending

        for (int tile = cid; tile < NTILES; tile += NCTA_B) {
            const int tch = tile / NT_PER_CH;
            const int nt  = tile - tch * NT_PER_CH;
            const int t0  = tch << 1;

            if (t0 < maxl) {
                const int n0 = nt << 6;
                unsigned long long acc[8][4] = {};

                for (int kc = 0; kc < 16; kc++) {
                    const int kb = kc << 5;
                    NBAR(2, 128);
                    #pragma unroll
                    for (int i = 0; i < 8; i++) {       // A: 128 rows x 32 k
                        int idx4 = tid2 + (i << 7);
                        int rr = idx4 >> 3, kq = idx4 & 7;
                        int bb = rr & 63, tt = t0 + (rr >> 6);
                        float4 v = *(const float4*)
                            &X[(size_t)((bb << 9) + tt) * 512 + kb + (kq << 2)];
                        float2 d;
                        d.x = v.x; d.y = v.x; *(float2*)&As2[((kq << 2) + 0) * 256 + 2 * rr] = d;
                        d.x = v.y; d.y = v.y; *(float2*)&As2[((kq << 2) + 1) * 256 + 2 * rr] = d;
                        d.x = v.z; d.y = v.z; *(float2*)&As2[((kq << 2) + 2) * 256 + 2 * rr] = d;
                        d.x = v.w; d.y = v.w; *(float2*)&As2[((kq << 2) + 3) * 256 + 2 * rr] = d;
                    }
                    #pragma unroll
                    for (int i = 0; i < 4; i++) {       // B: 64 rows x 32 k
                        int idx4 = tid2 + (i << 7);
                        int rr = idx4 >> 3, kq = idx4 & 7;
                        float4 w4 = *(const float4*)
                            &Wi[(size_t)(n0 + rr) * 512 + kb + (kq << 2)];
                        Bs[((kq << 2) + 0) * 64 + rr] = w4.x;
                        Bs[((kq << 2) + 1) * 64 + rr] = w4.y;
                        Bs[((kq << 2) + 2) * 64 + rr] = w4.z;
                        Bs[((kq << 2) + 3) * 64 + rr] = w4.w;
                    }
                    NBAR(2, 128);
                    #pragma unroll 4
                    for (int k = 0; k < 32; k++) {
                        unsigned long long av[8], bv[4];
                        ulonglong2 q;
                        q = *(const ulonglong2*)&As2[k * 256 + tm * 16 + 0];  av[0] = q.x; av[1] = q.y;
                        q = *(const ulonglong2*)&As2[k * 256 + tm * 16 + 4];  av[2] = q.x; av[3] = q.y;
                        q = *(const ulonglong2*)&As2[k * 256 + tm * 16 + 8];  av[4] = q.x; av[5] = q.y;
                        q = *(const ulonglong2*)&As2[k * 256 + tm * 16 + 12]; av[6] = q.x; av[7] = q.y;
                        q = *(const ulonglong2*)&Bs[k * 64 + tn * 8 + 0];     bv[0] = q.x; bv[1] = q.y;
                        q = *(const ulonglong2*)&Bs[k * 64 + tn * 8 + 4];     bv[2] = q.x; bv[3] = q.y;
                        #pragma unroll
                        for (int i = 0; i < 8; i++) {
                            #pragma unroll
                            for (int j = 0; j < 4; j++) FMA2(acc[i][j], av[i], bv[j]);
                        }
                    }
                }

                float4 bb0 = *(const float4*)&Bi[n0 + tn * 8];
                float4 bb1 = *(const float4*)&Bi[n0 + tn * 8 + 4];
                #pragma unroll
                for (int i = 0; i < 8; i++) {
                    int R = (tch << 7) + (tm << 3) + i;
                    float* dst = &g_proj[(size_t)R * NTOT + n0 + tn * 8];
                    float4 o0, o1;
                    o0.x = f2lo(acc[i][0]) + bb0.x; o0.y = f2hi(acc[i][0]) + bb0.y;
                    o0.z = f2lo(acc[i][1]) + bb0.z; o0.w = f2hi(acc[i][1]) + bb0.w;
                    o1.x = f2lo(acc[i][2]) + bb1.x; o1.y = f2hi(acc[i][2]) + bb1.y;
                    o1.z = f2lo(acc[i][3]) + bb1.z; o1.w = f2hi(acc[i][3]) + bb1.w;
                    *(float4*)dst = o0;
                    *(float4*)(dst + 4) = o1;
                }
            }

            NBAR(2, 128);                        // writes done before signal
            if (tid2 == 0) signal_release(&g_projcnt[tch]);
        }
    }
}

// ---------------------------------------------------------------------------
__global__ void init_kernel()
{
    int i = blockIdx.x * blockDim.x + threadIdx.x;
    if (i < NTCH) g_projcnt[i] = 0u;
    if (i < 8) g_cnt[i] = 0u;
}

extern "C" void kernel_launch(void* const* d_in, const int* in_sizes, int n_in,
                              void* d_out, int out_size)
{
    const float* x       = (const float*)d_in[0];
    const int*   lengths = (const int*)d_in[1];   // int32 or int64, auto-detected
    const float* w_in    = (const float*)d_in[2];
    const float* b_in    = (const float*)d_in[3];
    const float* w_state = (const float*)d_in[4];
    const float* b_state = (const float*)d_in[5];
    float* out = (float*)d_out;

    (void)in_sizes; (void)n_in; (void)out_size;

    init_kernel<<<1, 512>>>();

    size_t smemB = (size_t)SMEM_FLOATS * sizeof(float);
    cudaFuncSetAttribute(fused_kernel, cudaFuncAttributeMaxDynamicSharedMemorySize,
                         (int)smemB);
    fused_kernel<<<NCTA_B, NTHR, smemB>>>(x, lengths, w_in, b_in,
                                          w_state, b_state, out);
}

// round 14
// speedup vs baseline: 1.3238x; 1.3238x over previous
#include <cuda_runtime.h>
#include <math.h>
#include <stdint.h>
#include <stddef.h>

// ---------------------------------------------------------------------------
// AugmentedLstm: B=64, T=512, D=512, H=512
//   Kernel A: proj = X[32768,512] @ w_in^T -> [32768,3072] (+bias), fp32 FFMA2
//   Kernel B: persistent 128-CTA recurrence, 256 thr/CTA = 8 warps:
//             k-split pairs (warps q / q+4 take k halves of the same dots)
//             -> 2 warps per SMSP fill each other's issue stalls at IDENTICAL
//             SMEM traffic. Per-warp cp.async staging (warp-exclusive rows),
//             4-chunk pipeline, per-group release/acquire h counters,
//             SMEM partial-sum reduce between k-half partners.
// ---------------------------------------------------------------------------

#define BDIM 64
#define TDIM 512
#define HDIM 512
#define MTOT (BDIM * TDIM)   // 32768
#define NTOT (6 * HDIM)      // 3072
#define NCTA_B 128

// packed fp32x2 FMA (sm_100+/sm_103a PTX; ptxas never emits it from C++)
#define FMA2(d, a, b) asm("fma.rn.f32x2 %0, %1, %2, %0;" : "+l"(d) : "l"(a), "l"(b))

__device__ __forceinline__ float f2lo(unsigned long long v) {
    return __uint_as_float((unsigned)(v & 0xffffffffull));
}
__device__ __forceinline__ float f2hi(unsigned long long v) {
    return __uint_as_float((unsigned)(v >> 32));
}
__device__ __forceinline__ float sigm(float x) { return 1.0f / (1.0f + expf(-x)); }

// ---- global scratch (no runtime allocation allowed) ----
__device__ float g_proj[(size_t)MTOT * NTOT];     // 402 MB input projections
__device__ float g_hbuf[2][BDIM * HDIM];          // double-buffered h state
__device__ unsigned int g_cnt[8];                 // per-group step counters

__device__ __forceinline__ int read_len(const int* L, int b) {
    return (L[1] == 0) ? L[2 * b] : L[b];   // int64 vs int32 auto-detect
}

__device__ __forceinline__ void signal_release(unsigned* p) {
    unsigned t;
    asm volatile("atom.add.release.gpu.u32 %0, [%1], 1;" : "=r"(t) : "l"(p) : "memory");
}
__device__ __forceinline__ unsigned ld_acq(unsigned* p) {
    unsigned v;
    asm volatile("ld.acquire.gpu.u32 %0, [%1];" : "=r"(v) : "l"(p) : "memory");
    return v;
}
__device__ __forceinline__ void pollw(unsigned* p, unsigned tgt) {
    while ((int)(ld_acq(p) - tgt) < 0) { }
}

__device__ __forceinline__ void cpasync16(uint32_t dst, const float* src) {
    asm volatile("cp.async.cg.shared.global [%0], [%1], 16;" :: "r"(dst), "l"(src));
}
#define CP_COMMIT()  asm volatile("cp.async.commit_group;" ::: "memory")
#define CP_WAITG(n)  asm volatile("cp.async.wait_group " #n ";" ::: "memory")
#define NBAR(id, cnt) asm volatile("bar.sync %0, %1;" :: "r"(id), "r"(cnt) : "memory")

// ---------------------------------------------------------------------------
// Kernel A: 128x128 tile SGEMM with FFMA2 (A duplicated in SMEM so a2=(a,a))
// ---------------------------------------------------------------------------
__global__ __launch_bounds__(256)
void proj_kernel(const float* __restrict__ X, const int* __restrict__ L,
                 const float* __restrict__ W, const float* __restrict__ Bi)
{
    __shared__ float As2[32 * 256];   // [k][2*m] duplicated pairs
    __shared__ float Bs[32 * 128];    // [k][n]
    const int n0 = blockIdx.x * 128;
    const int m0 = blockIdx.y * 128;
    const int bidx = m0 >> 9;         // batch of this M tile (512 % 128 == 0)
    const int t0 = m0 & 511;
    if (read_len(L, bidx) <= t0) return;   // whole tile past this batch's length

    const int tid = threadIdx.x;
    const int tm = tid >> 4;          // 0..15
    const int tn = tid & 15;          // 0..15

    unsigned long long acc[8][4] = {};

    float4 ra[4], rb[4];
    #pragma unroll
    for (int i = 0; i < 4; i++) {     // prime chunk 0
        int idx4 = tid + (i << 8);
        int rr = idx4 >> 3, kq = idx4 & 7;
        ra[i] = *(const float4*)&X[(size_t)(m0 + rr) * 512 + (kq << 2)];
        rb[i] = *(const float4*)&W[(size_t)(n0 + rr) * 512 + (kq << 2)];
    }

    for (int kc = 0; kc < 16; kc++) {
        __syncthreads();
        #pragma unroll
        for (int i = 0; i < 4; i++) {
            int idx4 = tid + (i << 8);
            int rr = idx4 >> 3, kq = idx4 & 7;
            float4 v = ra[i];
            float2 d;
            d.x = v.x; d.y = v.x; *(float2*)&As2[((kq << 2) + 0) * 256 + 2 * rr] = d;
            d.x = v.y; d.y = v.y; *(float2*)&As2[((kq << 2) + 1) * 256 + 2 * rr] = d;
            d.x = v.z; d.y = v.z; *(float2*)&As2[((kq << 2) + 2) * 256 + 2 * rr] = d;
            d.x = v.w; d.y = v.w; *(float2*)&As2[((kq << 2) + 3) * 256 + 2 * rr] = d;
            float4 w4 = rb[i];
            Bs[((kq << 2) + 0) * 128 + rr] = w4.x;
            Bs[((kq << 2) + 1) * 128 + rr] = w4.y;
            Bs[((kq << 2) + 2) * 128 + rr] = w4.z;
            Bs[((kq << 2) + 3) * 128 + rr] = w4.w;
        }
        __syncthreads();
        if (kc < 15) {   // prefetch next chunk into registers during compute
            int kb = (kc + 1) << 5;
            #pragma unroll
            for (int i = 0; i < 4; i++) {
                int idx4 = tid + (i << 8);
                int rr = idx4 >> 3, kq = idx4 & 7;
                ra[i] = *(const float4*)&X[(size_t)(m0 + rr) * 512 + kb + (kq << 2)];
                rb[i] = *(const float4*)&W[(size_t)(n0 + rr) * 512 + kb + (kq << 2)];
            }
        }
        #pragma unroll 4
        for (int k = 0; k < 32; k++) {
            unsigned long long av[8], bv[4];
            ulonglong2 q;
            q = *(const ulonglong2*)&As2[k * 256 + tm * 16 + 0];  av[0] = q.x; av[1] = q.y;
            q = *(const ulonglong2*)&As2[k * 256 + tm * 16 + 4];  av[2] = q.x; av[3] = q.y;
            q = *(const ulonglong2*)&As2[k * 256 + tm * 16 + 8];  av[4] = q.x; av[5] = q.y;
            q = *(const ulonglong2*)&As2[k * 256 + tm * 16 + 12]; av[6] = q.x; av[7] = q.y;
            q = *(const ulonglong2*)&Bs[k * 128 + tn * 8 + 0];    bv[0] = q.x; bv[1] = q.y;
            q = *(const ulonglong2*)&Bs[k * 128 + tn * 8 + 4];    bv[2] = q.x; bv[3] = q.y;
            #pragma unroll
            for (int i = 0; i < 8; i++) {
                #pragma unroll
                for (int j = 0; j < 4; j++) FMA2(acc[i][j], av[i], bv[j]);
            }
        }
    }

    float4 bb0 = *(const float4*)&Bi[n0 + tn * 8];
    float4 bb1 = *(const float4*)&Bi[n0 + tn * 8 + 4];
    #pragma unroll
    for (int i = 0; i < 8; i++) {
        float* dst = &g_proj[(size_t)(m0 + tm * 8 + i) * NTOT + n0 + tn * 8];
        float4 o0, o1;
        o0.x = f2lo(acc[i][0]) + bb0.x; o0.y = f2hi(acc[i][0]) + bb0.y;
        o0.z = f2lo(acc[i][1]) + bb0.z; o0.w = f2hi(acc[i][1]) + bb0.w;
        o1.x = f2lo(acc[i][2]) + bb1.x; o1.y = f2hi(acc[i][2]) + bb1.y;
        o1.z = f2lo(acc[i][3]) + bb1.z; o1.w = f2hi(acc[i][3]) + bb1.w;
        *(float4*)dst = o0;
        *(float4*)(dst + 4) = o1;
    }
}

// ---------------------------------------------------------------------------
// Kernel B: persistent recurrence, 256 threads/CTA (8 warps).
// CTA cid owns output columns J=cid*4..cid*4+3 (20 w_state rows in SMEM).
// kh = tid>>7 selects k-half; within a half, (bp=tid7>>2, jl=tid7&3) computes
// partial (256-k) dots for batches 2bp, 2bp+1 across all 5 gates.
// Warp (kh,q): stages AND consumes exactly h rows 16q..16q+15, cols
// [256kh, 256kh+256) -> fully warp-self-contained staging, 4 chunk pipeline.
// Partials combined kh1 -> kh0 via SMEM (stride-11, conflict-free); kh0 does
// the gate epilogue and all stores. 2 warps/SMSP interleave at identical
// SMEM traffic -> fills the single-warp issue stalls.
// ---------------------------------------------------------------------------
#define SH_HSTRIDE 516   // %32==4, conflict-free h rows, 16B-aligned stride
#define SH_WSTRIDE 520   // %32==8
#define OFF_W   (BDIM * SH_HSTRIDE)          // 33024
#define OFF_LEN (OFF_W + 20 * SH_WSTRIDE)    // 43424
#define OFF_RED (OFF_LEN + 64)               // 43488
#define SMEM_FLOATS_B (OFF_RED + 128 * 11)   // 44896 floats = 179584 B
#define NTHR_B 256

#define ISSUE_CHUNK(G) do {                                                   \
    if (ral) {                                                                \
        int _kb = k0 + ((G) << 6) + soff;                                     \
        const float* _s = hb + _kb;                                           \
        uint32_t _d = hd + (uint32_t)(_kb << 2);                              \
        _Pragma("unroll")                                                     \
        for (int _i = 0; _i < 8; _i++) cpasync16(_d + (_i << 4), _s + (_i << 2)); \
    }                                                                         \
    CP_COMMIT();                                                              \
} while (0)

#define COMPUTE_CHUNK(G) do {                                                 \
    if (anyact) {                                                             \
        _Pragma("unroll 8")                                                   \
        for (int _kq = 0; _kq < 16; _kq++) {                                  \
            int _k = k0 + ((G) << 6) + (_kq << 2);                            \
            ulonglong2 hv0 = *(const ulonglong2*)&h0[_k];                     \
            ulonglong2 hv1 = *(const ulonglong2*)&h1[_k];                     \
            _Pragma("unroll")                                                 \
            for (int _g = 0; _g < 5; _g++) {                                  \
                ulonglong2 wv =                                               \
                    *(const ulonglong2*)&sh_w[(_g * 4 + jl) * SH_WSTRIDE + _k]; \
                FMA2(acc0[_g], hv0.x, wv.x);                                  \
                FMA2(acc0[_g], hv0.y, wv.y);                                  \
                FMA2(acc1[_g], hv1.x, wv.x);                                  \
                FMA2(acc1[_g], hv1.y, wv.y);                                  \
            }                                                                 \
        }                                                                     \
    }                                                                         \
} while (0)

__global__ __launch_bounds__(NTHR_B, 1)
void lstm_kernel(const int* __restrict__ L, const float* __restrict__ Ws,
                 const float* __restrict__ bs, float* __restrict__ out)
{
    extern __shared__ float sm[];
    float* sh_h = sm;
    float* sh_w = sm + OFF_W;
    int*   sh_len = (int*)(sm + OFF_LEN);
    float* sh_red = sm + OFF_RED;     // [128][11] partial sums from kh1

    const int cid  = blockIdx.x;      // 0..127
    const int tid  = threadIdx.x;     // 0..255
    const int kh   = tid >> 7;        // k-half: 0 or 1
    const int tid7 = tid & 127;
    const int bp   = tid7 >> 2;       // 0..31 (batch pair)
    const int jl   = tid7 & 3;
    const int b0   = bp << 1;
    const int b1   = b0 + 1;
    const int J    = (cid << 2) + jl;
    const int k0   = kh << 8;         // 0 or 256
    const int mygrp = cid >> 4;

    const int lane = tid & 31;
    const int q    = (tid >> 5) & 3;                   // warp within half
    const int srow = (q << 4) + (lane >> 1);           // staged/consumed row
    const int soff = (lane & 1) << 5;                  // 0/32 floats in chunk
    const uint32_t sh_h_u32 = (uint32_t)__cvta_generic_to_shared(sh_h);

    if (tid < BDIM) sh_len[tid] = read_len(L, tid);
    for (int i = tid; i < BDIM * SH_HSTRIDE; i += NTHR_B) sh_h[i] = 0.0f;
    for (int idx4 = tid; idx4 < 20 * 128; idx4 += NTHR_B) {
        int r = idx4 >> 7;
        int k = (idx4 & 127) << 2;
        int grow = ((r >> 2) << 9) + (cid << 2) + (r & 3);
        *(float4*)&sh_w[r * SH_WSTRIDE + k] = *(const float4*)&Ws[(size_t)grow * 512 + k];
    }
    __syncthreads();

    const int len0 = sh_len[b0];
    const int len1 = sh_len[b1];
    const int wlen = sh_len[q << 4];   // longest length among this warp's rows
    float bias[5];
    #pragma unroll
    for (int g = 0; g < 5; g++) bias[g] = bs[g * 512 + J];
    float c0 = 0.0f, c1 = 0.0f;

    const float* h0 = &sh_h[b0 * SH_HSTRIDE];
    const float* h1 = &sh_h[b1 * SH_HSTRIDE];

    for (int t = 0; t < TDIM; t++) {
        const bool a0 = (t < len0);
        const bool a1 = (t < len1);
        const bool anyact = a0 | a1;

        // pi loads: only the epilogue half (kh0) needs them
        float pi0[6], pi1[6];
        if (kh == 0) {
            if (a0) {
                const float* p = &g_proj[(size_t)((b0 << 9) + t) * NTOT + J];
                #pragma unroll
                for (int g = 0; g < 6; g++) pi0[g] = p[g * 512];
            }
            if (a1) {
                const float* p = &g_proj[(size_t)((b1 << 9) + t) * NTOT + J];
                #pragma unroll
                for (int g = 0; g < 6; g++) pi1[g] = p[g * 512];
            }
        }

        unsigned long long acc0[5] = {}, acc1[5] = {};

        if (t > 0 && wlen > t) {
            const unsigned tgt = 16u * (unsigned)t;
            const bool ral = (sh_len[srow] > t);
            const float* hb = &g_hbuf[t & 1][srow << 9];
            const uint32_t hd = sh_h_u32 + (uint32_t)(srow * SH_HSTRIDE) * 4u;
            unsigned* gc = &g_cnt[kh << 2];

            pollw(gc + 0, tgt); ISSUE_CHUNK(0);
            pollw(gc + 1, tgt); ISSUE_CHUNK(1);
            CP_WAITG(1); __syncwarp(); COMPUTE_CHUNK(0);
            pollw(gc + 2, tgt); ISSUE_CHUNK(2);
            CP_WAITG(1); __syncwarp(); COMPUTE_CHUNK(1);
            pollw(gc + 3, tgt); ISSUE_CHUNK(3);
            CP_WAITG(1); __syncwarp(); COMPUTE_CHUNK(2);
            CP_WAITG(0); __syncwarp(); COMPUTE_CHUNK(3);
        }
        // t == 0: h == 0 -> partials stay zero.

        if (kh == 1) {                     // publish partials (zeros if dead)
            float* r = &sh_red[tid7 * 11];
            #pragma unroll
            for (int g = 0; g < 5; g++) {
                r[g]     = f2lo(acc0[g]) + f2hi(acc0[g]);
                r[5 + g] = f2lo(acc1[g]) + f2hi(acc1[g]);
            }
        }
        NBAR(1, NTHR_B);

        if (kh == 0) {
            const float* r = &sh_red[tid7 * 11];
            float outv0 = 0.0f, outv1 = 0.0f;
            if (a0) {
                float ps[5];
                #pragma unroll
                for (int g = 0; g < 5; g++)
                    ps[g] = f2lo(acc0[g]) + f2hi(acc0[g]) + r[g] + bias[g];
                float ig = sigm(pi0[0] + ps[0]);
                float fg = sigm(pi0[1] + ps[1]);
                float gg = tanhf(pi0[2] + ps[2]);
                float og = sigm(pi0[3] + ps[3]);
                float cn = ig * gg + fg * c0;
                float ov = og * tanhf(cn);
                float hw = sigm(pi0[4] + ps[4]);
                outv0 = hw * ov + (1.0f - hw) * pi0[5];
                c0 = cn;
                __stcg(&g_hbuf[(t + 1) & 1][(b0 << 9) + J], outv0);
            } else c0 = 0.0f;
            if (a1) {
                float ps[5];
                #pragma unroll
                for (int g = 0; g < 5; g++)
                    ps[g] = f2lo(acc1[g]) + f2hi(acc1[g]) + r[5 + g] + bias[g];
                float ig = sigm(pi1[0] + ps[0]);
                float fg = sigm(pi1[1] + ps[1]);
                float gg = tanhf(pi1[2] + ps[2]);
                float og = sigm(pi1[3] + ps[3]);
                float cn = ig * gg + fg * c1;
                float ov = og * tanhf(cn);
                float hw = sigm(pi1[4] + ps[4]);
                outv1 = hw * ov + (1.0f - hw) * pi1[5];
                c1 = cn;
                __stcg(&g_hbuf[(t + 1) & 1][(b1 << 9) + J], outv1);
            } else c1 = 0.0f;
            out[(size_t)((b0 << 9) + t) * HDIM + J] = outv0;
            out[(size_t)((b1 << 9) + t) * HDIM + J] = outv1;
        }

        NBAR(1, NTHR_B);                 // h stores done + sh_red consumed
        if (tid == 0 && t != TDIM - 1) signal_release(&g_cnt[mygrp]);
    }
}

// ---------------------------------------------------------------------------
__global__ void init_kernel()
{
    if (threadIdx.x < 8) g_cnt[threadIdx.x] = 0u;
}

extern "C" void kernel_launch(void* const* d_in, const int* in_sizes, int n_in,
                              void* d_out, int out_size)
{
    const float* x       = (const float*)d_in[0];
    const int*   lengths = (const int*)d_in[1];   // int32 or int64, auto-detected
    const float* w_in    = (const float*)d_in[2];
    const float* b_in    = (const float*)d_in[3];
    const float* w_state = (const float*)d_in[4];
    const float* b_state = (const float*)d_in[5];
    float* out = (float*)d_out;

    (void)in_sizes; (void)n_in; (void)out_size;

    init_kernel<<<1, 32>>>();

    dim3 gA(NTOT / 128, MTOT / 128);  // 24 x 256
    proj_kernel<<<gA, 256>>>(x, lengths, w_in, b_in);

    size_t smemB = (size_t)SMEM_FLOATS_B * sizeof(float);
    cudaFuncSetAttribute(lstm_kernel, cudaFuncAttributeMaxDynamicSharedMemorySize,
                         (int)smemB);
    lstm_kernel<<<NCTA_B, NTHR_B, smemB>>>(lengths, w_state, b_state, out);
}